// round 2
// baseline (speedup 1.0000x reference)
#include <cuda_runtime.h>

#define B 32
#define S 1024
#define W 512
#define D 768
#define NPOS 32
#define CW 8            // words per CTA
#define NT 192          // = D/4 threads, one float4 column each

__global__ void __launch_bounds__(NT) charpool_stream_kernel(
    const float* __restrict__ feats,      // [B, S, D]
    const int* __restrict__ word_lens,    // [B, W]
    const int* __restrict__ seq_len,      // [B]
    const int* __restrict__ pos,          // [B, W]
    const float* __restrict__ pos_table,  // [NPOS, D]
    float* __restrict__ out)              // [B, W, D]
{
    const int g = blockIdx.x;
    const int b = blockIdx.y;
    const int t = threadIdx.x;
    const int w0 = g * CW;

    // Word boundary metadata (uniform across threads; small L2-hot arrays)
    int st[CW + 1];
    #pragma unroll
    for (int j = 0; j <= CW; ++j) {
        const int w = w0 + j;
        st[j] = (w < W) ? word_lens[b * W + w] : 0;
    }
    const int sl = seq_len[b];

    int en[CW];
    #pragma unroll
    for (int j = 0; j < CW; ++j)
        en[j] = (st[j + 1] == 0) ? sl : st[j + 1];

    // valid words form a prefix of the group; find last valid index
    int lv = -1;
    #pragma unroll
    for (int j = 0; j < CW; ++j)
        if ((st[j] != 0) || (w0 + j == 0)) lv = j;

    float4* outp = reinterpret_cast<float4*>(out + ((size_t)b * W + w0) * D) + t;
    const float4* ptab = reinterpret_cast<const float4*>(pos_table);

    int cur = 0;
    if (lv >= 0) {
        int s = st[0];
        const int g_end = en[lv];
        const float4* fp = reinterpret_cast<const float4*>(
            feats + ((size_t)b * S + (size_t)s) * D) + t;
        float4 acc = make_float4(0.f, 0.f, 0.f, 0.f);

        while (s < g_end) {
            // batch-of-4 loads: independent, MLP=4 on the HBM stream
            float4 v[4];
            #pragma unroll
            for (int i = 0; i < 4; ++i) {
                if (s + i < g_end) v[i] = fp[i * (D / 4)];
                else               v[i] = make_float4(0.f, 0.f, 0.f, 0.f);
            }
            #pragma unroll
            for (int i = 0; i < 4; ++i) {
                if (s + i >= g_end) break;
                if (s + i == en[cur]) {
                    // flush word 'cur' (boundary reached)
                    const float inv = 1.0f / (float)(en[cur] - st[cur]);
                    const int p = pos[b * W + w0 + cur];
                    const float4 pt = ptab[p * (D / 4) + t];
                    float4 r;
                    r.x = acc.x * inv + pt.x;
                    r.y = acc.y * inv + pt.y;
                    r.z = acc.z * inv + pt.z;
                    r.w = acc.w * inv + pt.w;
                    outp[cur * (D / 4)] = r;
                    acc = make_float4(0.f, 0.f, 0.f, 0.f);
                    ++cur;
                }
                acc.x += v[i].x; acc.y += v[i].y;
                acc.z += v[i].z; acc.w += v[i].w;
            }
            s  += 4;
            fp += 4 * (D / 4);
        }
        // final flush: word 'cur' (== lv)
        {
            int len = en[cur] - st[cur];
            if (len < 1) len = 1;
            const float inv = 1.0f / (float)len;
            const int p = pos[b * W + w0 + cur];
            const float4 pt = ptab[p * (D / 4) + t];
            float4 r;
            r.x = acc.x * inv + pt.x;
            r.y = acc.y * inv + pt.y;
            r.z = acc.z * inv + pt.z;
            r.w = acc.w * inv + pt.w;
            outp[cur * (D / 4)] = r;
            ++cur;
        }
    }

    // trailing invalid (padding) words: output = pos_table[pos] (pos=0 row is zero)
    for (int j = cur; j < CW; ++j) {
        const int p = pos[b * W + w0 + j];
        outp[j * (D / 4)] = ptab[p * (D / 4) + t];
    }
}

extern "C" void kernel_launch(void* const* d_in, const int* in_sizes, int n_in,
                              void* d_out, int out_size)
{
    const float* feats     = (const float*)d_in[0];
    const int*   word_lens = (const int*)d_in[1];
    const int*   seq_len   = (const int*)d_in[2];
    const int*   pos       = (const int*)d_in[3];
    const float* pos_table = (const float*)d_in[4];
    float* out = (float*)d_out;

    dim3 grid(W / CW, B);
    charpool_stream_kernel<<<grid, NT>>>(feats, word_lens, seq_len, pos, pos_table, out);
}

// round 3
// speedup vs baseline: 1.1975x; 1.1975x over previous
#include <cuda_runtime.h>

#define B 32
#define S 1024
#define W 512
#define D 768
#define NPOS 32
#define NT 192           // = D/4 threads, one float4 column per thread
#define TOTW (B * W)     // 16384 words
#define NBLK 1480        // ~10 CTAs per SM on 148-SM sm_100a, single wave

__global__ void __launch_bounds__(NT) charpool_persist_kernel(
    const float* __restrict__ feats,      // [B, S, D]
    const int* __restrict__ word_lens,    // [B, W]
    const int* __restrict__ seq_len,      // [B]
    const int* __restrict__ pos,          // [B, W]
    const float* __restrict__ pos_table,  // [NPOS, D]
    float* __restrict__ out)              // [B, W, D]
{
    const int t = threadIdx.x;
    const float4* __restrict__ ptab = reinterpret_cast<const float4*>(pos_table);

    int id = blockIdx.x;
    if (id >= TOTW) return;

    // metadata for first word
    int start = __ldg(&word_lens[id]);
    int nxt   = ((id & (W - 1)) + 1 < W) ? __ldg(&word_lens[id + 1]) : 0;
    int p     = __ldg(&pos[id]);
    int sl    = __ldg(&seq_len[id >> 9]);

    for (;;) {
        // ---- prefetch next word's metadata (overlaps current feats latency) ----
        const int nid  = id + NBLK;
        const bool more = (nid < TOTW);
        int n_start = 0, n_nxt = 0, n_p = 0, n_sl = 0;
        if (more) {
            n_start = __ldg(&word_lens[nid]);
            n_nxt   = ((nid & (W - 1)) + 1 < W) ? __ldg(&word_lens[nid + 1]) : 0;
            n_p     = __ldg(&pos[nid]);
            n_sl    = __ldg(&seq_len[nid >> 9]);
        }

        // ---- process current word ----
        const int b   = id >> 9;
        const int w   = id & (W - 1);
        const int end = (nxt == 0) ? sl : nxt;
        const bool valid = (start != 0) || (w == 0);

        const float4 pt = ptab[p * (D / 4) + t];
        float4 r;

        if (valid) {
            int len = end - start;
            if (len < 1) len = 1;
            const float4* fp = reinterpret_cast<const float4*>(
                feats + ((size_t)b * S + (size_t)start) * D) + t;

            float4 acc = make_float4(0.f, 0.f, 0.f, 0.f);
            for (int s = 0; s < len; s += 4) {
                // issue up to 4 independent row loads before accumulating (MLP=4)
                float4 v0, v1, v2, v3;
                v0 = fp[0 * (D / 4)];
                v1 = (s + 1 < len) ? fp[1 * (D / 4)] : make_float4(0.f, 0.f, 0.f, 0.f);
                v2 = (s + 2 < len) ? fp[2 * (D / 4)] : make_float4(0.f, 0.f, 0.f, 0.f);
                v3 = (s + 3 < len) ? fp[3 * (D / 4)] : make_float4(0.f, 0.f, 0.f, 0.f);
                acc.x += (v0.x + v1.x) + (v2.x + v3.x);
                acc.y += (v0.y + v1.y) + (v2.y + v3.y);
                acc.z += (v0.z + v1.z) + (v2.z + v3.z);
                acc.w += (v0.w + v1.w) + (v2.w + v3.w);
                fp += 4 * (D / 4);
            }
            const float inv = 1.0f / (float)len;
            r.x = fmaf(acc.x, inv, pt.x);
            r.y = fmaf(acc.y, inv, pt.y);
            r.z = fmaf(acc.z, inv, pt.z);
            r.w = fmaf(acc.w, inv, pt.w);
        } else {
            r = pt;  // pos=0 row of the table is zero -> zeros for padding words
        }

        reinterpret_cast<float4*>(out + (size_t)id * D)[t] = r;

        if (!more) break;
        id = nid;
        start = n_start; nxt = n_nxt; p = n_p; sl = n_sl;
    }
}

extern "C" void kernel_launch(void* const* d_in, const int* in_sizes, int n_in,
                              void* d_out, int out_size)
{
    const float* feats     = (const float*)d_in[0];
    const int*   word_lens = (const int*)d_in[1];
    const int*   seq_len   = (const int*)d_in[2];
    const int*   pos       = (const int*)d_in[3];
    const float* pos_table = (const float*)d_in[4];
    float* out = (float*)d_out;

    charpool_persist_kernel<<<NBLK, NT>>>(feats, word_lens, seq_len, pos, pos_table, out);
}